// round 16
// baseline (speedup 1.0000x reference)
#include <cuda_runtime.h>
#include <cuda_fp16.h>
#include <cstdint>

// ---------------- problem constants ----------------
#define QTOT   13294
#define BATCH  2
#define BQ     (BATCH*QTOT)   // 26588
#define DMODEL 256
#define NH     8
#define HD     32
#define DFF    1024
#define NLAYERS 6

__constant__ int c_start[4] = {0, 10000, 12500, 13125};
__constant__ int c_H[4]     = {100, 50, 25, 13};
__constant__ int c_W[4]     = {100, 50, 25, 13};

// ---------------- device scratch ----------------
__device__ float  g_x[BQ * DMODEL];
__device__ float  g_pos[BQ * DMODEL];
__device__ float  g_offlog[BQ * 384];
__device__ float  g_attnout[BQ * DMODEL];
__device__ float  g_ff2[BQ * DMODEL];
__device__ float  g_ref[QTOT * 2];
__device__ float  g_bcomb[NLAYERS * 384];
__device__ __half g_xh[BQ * DMODEL];
__device__ __half g_valh[BQ * DMODEL];
__device__ __half g_samph[BQ * DMODEL];
__device__ __half g_ffh[BQ * DFF];
#define WT_LAYER 753664
#define OFF_WOA 0
#define OFF_WV  98304
#define OFF_WO  163840
#define OFF_W1  229376
#define OFF_W2  491520
__device__ __half g_wt[NLAYERS * WT_LAYER];

// ---------------- helpers ----------------
__device__ __forceinline__ float wredsum(float v) {
    #pragma unroll
    for (int o = 16; o; o >>= 1) v += __shfl_xor_sync(0xffffffffu, v, o);
    return v;
}
__device__ __forceinline__ uint32_t smem_u32(const void* p) {
    uint32_t a;
    asm("{ .reg .u64 t; cvta.to.shared.u64 t, %1; cvt.u32.u64 %0, t; }" : "=r"(a) : "l"(p));
    return a;
}
#define LDSM4(r, addr) \
    asm volatile("ldmatrix.sync.aligned.m8n8.x4.shared.b16 {%0,%1,%2,%3}, [%4];" \
        : "=r"((r)[0]), "=r"((r)[1]), "=r"((r)[2]), "=r"((r)[3]) : "r"(addr))

__device__ __forceinline__ void mma_f16(float* c, const uint32_t* a, const uint32_t* b) {
    asm volatile(
        "mma.sync.aligned.m16n8k16.row.col.f32.f16.f16.f32 "
        "{%0,%1,%2,%3}, {%4,%5,%6,%7}, {%8,%9}, {%0,%1,%2,%3};"
        : "+f"(c[0]), "+f"(c[1]), "+f"(c[2]), "+f"(c[3])
        : "r"(a[0]), "r"(a[1]), "r"(a[2]), "r"(a[3]), "r"(b[0]), "r"(b[1]));
}
__device__ __forceinline__ uint32_t packh2(float a, float b) {
    __half2 h = __floats2half2_rn(a, b);
    return *reinterpret_cast<uint32_t*>(&h);
}
__device__ __forceinline__ void cpasync16(uint32_t dst, const void* src) {
    asm volatile("cp.async.cg.shared.global [%0], [%1], 16;"
                 :: "r"(dst), "l"(src) : "memory");
}
#define CP_COMMIT() asm volatile("cp.async.commit_group;" ::: "memory")
#define CP_WAIT0()  asm volatile("cp.async.wait_group 0;" ::: "memory")
#define CP_WAIT1()  asm volatile("cp.async.wait_group 1;" ::: "memory")

// ---------------- flatten ----------------
__global__ void flatten_kernel(float* __restrict__ px, __half* __restrict__ pxh,
                               float* __restrict__ ppos,
                               const float* __restrict__ src, const float* __restrict__ pos,
                               const float* __restrict__ le, int start, int hw) {
    int idx = blockIdx.x * blockDim.x + threadIdx.x;
    int total = BATCH * hw * DMODEL;
    if (idx >= total) return;
    int d = idx & 255;
    int p = (idx >> 8) % hw;
    int b = idx / (DMODEL * hw);
    size_t sidx = ((size_t)b * DMODEL + d) * hw + p;
    size_t tok  = (size_t)b * QTOT + start + p;
    float v = src[sidx];
    px[tok * DMODEL + d]  = v;
    pxh[tok * DMODEL + d] = __float2half_rn(v);
    ppos[tok * DMODEL + d] = pos[sidx] + le[d];
}

// ---------------- reference points ----------------
__global__ void ref_kernel(float* __restrict__ pref) {
    int q = blockIdx.x * blockDim.x + threadIdx.x;
    if (q >= QTOT) return;
    int l = 3;
    if (q < 10000) l = 0; else if (q < 12500) l = 1; else if (q < 13125) l = 2;
    int loc = q - c_start[l];
    int W = c_W[l];
    int yy = loc / W, xx = loc - yy * W;
    pref[2 * q]     = (xx + 0.5f) / (float)c_W[l];
    pref[2 * q + 1] = (yy + 0.5f) / (float)c_H[l];
}

// ---------------- weight packing ----------------
__global__ void transpose_woa(__half* __restrict__ pwt,
                              const float* __restrict__ woff, const float* __restrict__ wattn) {
    int idx = blockIdx.x * blockDim.x + threadIdx.x;
    int total = NLAYERS * 384 * 256;
    if (idx >= total) return;
    int l = idx / (384 * 256);
    int rem = idx - l * 384 * 256;
    int n = rem >> 8, k = rem & 255;
    float v = (n < 256) ? woff[(size_t)l * 65536 + k * 256 + n]
                        : wattn[(size_t)l * 32768 + k * 128 + (n - 256)];
    pwt[(size_t)l * WT_LAYER + OFF_WOA + n * 256 + k] = __float2half_rn(v);
}
__global__ void transpose_nl(__half* __restrict__ out, const float* __restrict__ in,
                             int K, int N) {
    int idx = blockIdx.x * blockDim.x + threadIdx.x;
    int total = NLAYERS * N * K;
    if (idx >= total) return;
    int l = idx / (N * K);
    int rem = idx - l * N * K;
    int n = rem / K, k = rem - n * K;
    out[(size_t)l * WT_LAYER + n * K + k] = __float2half_rn(in[(size_t)l * K * N + k * N + n]);
}
__global__ void bias_comb_kernel(float* __restrict__ out, const float* __restrict__ boff,
                                 const float* __restrict__ battn) {
    int idx = blockIdx.x * blockDim.x + threadIdx.x;
    if (idx >= NLAYERS * 384) return;
    int l = idx / 384, j = idx - l * 384;
    out[idx] = (j < 256) ? boff[l * 256 + j] : battn[l * 128 + (j - 256)];
}

// ---------------- persistent fp16 mma.sync GEMM ----------------
// block 128x128, 8 warps (2M x 4N), warp tile 64x32, mma m16n8k16, KC=32,
// reg-double-buffered staging (FUSE) / cp.async 2-stage (non-FUSE).
// Persistent: fixed grid, each CTA loops over output tiles (kills wave quantization).
#define TM 128
#define TN 128
#define ASTR 40
#define BSTR 40
#define PERSIST_CTAS 296

template<bool RELU, bool HALF_OUT, bool FUSE>
__global__ void __launch_bounds__(256) gemm_h_kernel(
    const void* __restrict__ Av, const float* __restrict__ A2,
    const __half* __restrict__ Bt,
    const float* __restrict__ bias, void* __restrict__ Cv,
    int M, int N, int K)
{
    __shared__ __align__(16) __half smA[2][TM * ASTR];
    __shared__ __align__(16) __half smB[2][TN * BSTR];

    int tid = threadIdx.x;
    int wid = tid >> 5, lane = tid & 31;
    int wm = wid & 1, wn = wid >> 1;          // 2 M-warps x 4 N-warps
    int NC = K >> 5;
    int mtiles = (M + TM - 1) / TM;
    int ntiles = mtiles * (N / TN);

    int arow = tid >> 1, ahalf = tid & 1;     // 2 threads per row, 16 halves each
    uint32_t aDst[2], bDst[2];
    #pragma unroll
    for (int s = 0; s < 2; ++s) {
        aDst[s] = smem_u32(&smA[s][arow * ASTR + ahalf * 16]);
        bDst[s] = smem_u32(&smB[s][arow * BSTR + ahalf * 16]);
    }
    int sub = lane >> 3, lrow = lane & 7;

    for (int t = blockIdx.x; t < ntiles; t += gridDim.x) {
        int m0 = (t % mtiles) * TM;
        int n0 = (t / mtiles) * TN;

        int aRowG = m0 + arow;
        int aRowC = (aRowG < M) ? aRowG : (M - 1);
        int bRowG = n0 + arow;

        float acc[4][4][4];
        #pragma unroll
        for (int i = 0; i < 4; ++i)
            #pragma unroll
            for (int j = 0; j < 4; ++j)
                #pragma unroll
                for (int r = 0; r < 4; ++r) acc[i][j][r] = 0.f;

        uint4 ra0, ra1, rb0, rb1;

        if (FUSE) {
            const float* x = (const float*)Av + (size_t)aRowC * K + ahalf * 16;
            const float* p = A2 + (size_t)aRowC * K + ahalf * 16;
            float4 x0 = *(const float4*)(x), x1 = *(const float4*)(x + 4);
            float4 x2 = *(const float4*)(x + 8), x3 = *(const float4*)(x + 12);
            float4 p0 = *(const float4*)(p), p1 = *(const float4*)(p + 4);
            float4 p2 = *(const float4*)(p + 8), p3 = *(const float4*)(p + 12);
            ra0.x = packh2(x0.x + p0.x, x0.y + p0.y); ra0.y = packh2(x0.z + p0.z, x0.w + p0.w);
            ra0.z = packh2(x1.x + p1.x, x1.y + p1.y); ra0.w = packh2(x1.z + p1.z, x1.w + p1.w);
            ra1.x = packh2(x2.x + p2.x, x2.y + p2.y); ra1.y = packh2(x2.z + p2.z, x2.w + p2.w);
            ra1.z = packh2(x3.x + p3.x, x3.y + p3.y); ra1.w = packh2(x3.z + p3.z, x3.w + p3.w);
            const uint4* bG = (const uint4*)&Bt[(size_t)bRowG * K + ahalf * 16];
            rb0 = bG[0]; rb1 = bG[1];
        } else {
            const char* aS = (const char*)((const __half*)Av + (size_t)aRowC * K + ahalf * 16);
            const char* bS = (const char*)&Bt[(size_t)bRowG * K + ahalf * 16];
            cpasync16(aDst[0],      aS);
            cpasync16(aDst[0] + 16, aS + 16);
            cpasync16(bDst[0],      bS);
            cpasync16(bDst[0] + 16, bS + 16);
            CP_COMMIT();
        }

        for (int c = 0; c < NC; ++c) {
            int buf = c & 1;
            if (FUSE) {
                *reinterpret_cast<uint4*>(&smA[buf][arow * ASTR + ahalf * 16])     = ra0;
                *reinterpret_cast<uint4*>(&smA[buf][arow * ASTR + ahalf * 16 + 8]) = ra1;
                *reinterpret_cast<uint4*>(&smB[buf][arow * BSTR + ahalf * 16])     = rb0;
                *reinterpret_cast<uint4*>(&smB[buf][arow * BSTR + ahalf * 16 + 8]) = rb1;
                if (c + 1 < NC) {
                    int ko = (c + 1) * 32 + ahalf * 16;
                    const float* x = (const float*)Av + (size_t)aRowC * K + ko;
                    const float* p = A2 + (size_t)aRowC * K + ko;
                    float4 x0 = *(const float4*)(x), x1 = *(const float4*)(x + 4);
                    float4 x2 = *(const float4*)(x + 8), x3 = *(const float4*)(x + 12);
                    float4 p0 = *(const float4*)(p), p1 = *(const float4*)(p + 4);
                    float4 p2 = *(const float4*)(p + 8), p3 = *(const float4*)(p + 12);
                    ra0.x = packh2(x0.x + p0.x, x0.y + p0.y); ra0.y = packh2(x0.z + p0.z, x0.w + p0.w);
                    ra0.z = packh2(x1.x + p1.x, x1.y + p1.y); ra0.w = packh2(x1.z + p1.z, x1.w + p1.w);
                    ra1.x = packh2(x2.x + p2.x, x2.y + p2.y); ra1.y = packh2(x2.z + p2.z, x2.w + p2.w);
                    ra1.z = packh2(x3.x + p3.x, x3.y + p3.y); ra1.w = packh2(x3.z + p3.z, x3.w + p3.w);
                    const uint4* bG = (const uint4*)&Bt[(size_t)bRowG * K + ko];
                    rb0 = bG[0]; rb1 = bG[1];
                }
                __syncthreads();
            } else {
                if (c + 1 < NC) {
                    int ko = (c + 1) * 32 + ahalf * 16;
                    int nxt = (c + 1) & 1;
                    const char* aS = (const char*)((const __half*)Av + (size_t)aRowC * K + ko);
                    const char* bS = (const char*)&Bt[(size_t)bRowG * K + ko];
                    cpasync16(aDst[nxt],      aS);
                    cpasync16(aDst[nxt] + 16, aS + 16);
                    cpasync16(bDst[nxt],      bS);
                    cpasync16(bDst[nxt] + 16, bS + 16);
                    CP_COMMIT();
                    CP_WAIT1();
                } else {
                    CP_WAIT0();
                }
                __syncthreads();
            }

            const __half* As = smA[buf];
            const __half* Bs = smB[buf];
            #pragma unroll
            for (int ks = 0; ks < 2; ++ks) {
                uint32_t af[4][4];
                #pragma unroll
                for (int mt = 0; mt < 4; ++mt) {
                    int r = wm * 64 + mt * 16 + ((sub & 1) << 3) + lrow;
                    int col = ks * 16 + ((sub >> 1) << 3);
                    LDSM4(af[mt], smem_u32(&As[r * ASTR + col]));
                }
                uint32_t bf[4][2];
                #pragma unroll
                for (int g = 0; g < 2; ++g) {
                    int nr = wn * 32 + ((g * 2 + (sub >> 1)) << 3) + lrow;
                    int col = ks * 16 + ((sub & 1) << 3);
                    uint32_t tt[4];
                    LDSM4(tt, smem_u32(&Bs[nr * BSTR + col]));
                    bf[g * 2 + 0][0] = tt[0]; bf[g * 2 + 0][1] = tt[1];
                    bf[g * 2 + 1][0] = tt[2]; bf[g * 2 + 1][1] = tt[3];
                }
                #pragma unroll
                for (int mt = 0; mt < 4; ++mt)
                    #pragma unroll
                    for (int nt = 0; nt < 4; ++nt)
                        mma_f16(acc[mt][nt], af[mt], bf[nt]);
            }
            __syncthreads();
        }

        // epilogue (no smem use — safe before next tile's staging)
        #pragma unroll
        for (int mt = 0; mt < 4; ++mt) {
            int r0 = m0 + wm * 64 + mt * 16 + (lane >> 2);
            int r1 = r0 + 8;
            #pragma unroll
            for (int nt = 0; nt < 4; ++nt) {
                int cb = n0 + wn * 32 + nt * 8 + 2 * (lane & 3);
                float b0 = bias[cb], b1 = bias[cb + 1];
                float v0 = acc[mt][nt][0] + b0;
                float v1 = acc[mt][nt][1] + b1;
                float v2 = acc[mt][nt][2] + b0;
                float v3 = acc[mt][nt][3] + b1;
                if (RELU) {
                    v0 = fmaxf(v0, 0.f); v1 = fmaxf(v1, 0.f);
                    v2 = fmaxf(v2, 0.f); v3 = fmaxf(v3, 0.f);
                }
                if (HALF_OUT) {
                    __half* Ch = (__half*)Cv;
                    if (r0 < M)
                        *reinterpret_cast<__half2*>(&Ch[(size_t)r0 * N + cb]) = __floats2half2_rn(v0, v1);
                    if (r1 < M)
                        *reinterpret_cast<__half2*>(&Ch[(size_t)r1 * N + cb]) = __floats2half2_rn(v2, v3);
                } else {
                    float* Cf = (float*)Cv;
                    if (r0 < M)
                        *reinterpret_cast<float2*>(&Cf[(size_t)r0 * N + cb]) = make_float2(v0, v1);
                    if (r1 < M)
                        *reinterpret_cast<float2*>(&Cf[(size_t)r1 * N + cb]) = make_float2(v2, v3);
                }
            }
        }
    }
}

// ---------------- deformable attention sampling (dual-head, half2) ----------------
__global__ void deform_kernel(const __half* __restrict__ pvalh, const float* __restrict__ pol,
                              const float* __restrict__ pref, __half* __restrict__ psamph) {
    int gwarp = (blockIdx.x * blockDim.x + threadIdx.x) >> 5;
    int lane = threadIdx.x & 31;
    if (gwarp >= BATCH * QTOT * (NH / 2)) return;
    int hp = gwarp % (NH / 2);
    int q = (gwarp / (NH / 2)) % QTOT;
    int b = gwarp / ((NH / 2) * QTOT);
    int h = hp * 2 + (lane >> 4);
    int ch = (lane & 15) * 2;
    size_t tok = (size_t)b * QTOT + q;

    const float* orow = &pol[tok * 384 + h * 32];
    const float* lrow = &pol[tok * 384 + 256 + h * 16];

    float lg[16];
    float mx = -1e30f;
    #pragma unroll
    for (int i = 0; i < 16; ++i) { lg[i] = __ldg(&lrow[i]); mx = fmaxf(mx, lg[i]); }
    float ssum = 0.f;
    #pragma unroll
    for (int i = 0; i < 16; ++i) { lg[i] = expf(lg[i] - mx); ssum += lg[i]; }
    float inv = 1.f / ssum;

    float rx = pref[2 * q];
    float ry = pref[2 * q + 1];

    float accx = 0.f, accy = 0.f;
    #pragma unroll
    for (int p = 0; p < 16; ++p) {
        int l = p >> 2;
        float w  = lg[p] * inv;
        float ox = __ldg(&orow[2 * p]);
        float oy = __ldg(&orow[2 * p + 1]);
        int Wl = c_W[l], Hl = c_H[l];
        float fw = (float)Wl, fh = (float)Hl;
        float x = (rx + ox / fw) * fw - 0.5f;
        float y = (ry + oy / fh) * fh - 0.5f;
        float x0f = floorf(x), y0f = floorf(y);
        int x0 = (int)x0f, y0 = (int)y0f;
        float fx = x - x0f, fy = y - y0f;
        size_t base = (size_t)b * QTOT + c_start[l];
        #pragma unroll
        for (int dy = 0; dy < 2; ++dy) {
            #pragma unroll
            for (int dx = 0; dx < 2; ++dx) {
                int xi = x0 + dx, yi = y0 + dy;
                if (xi >= 0 && xi < Wl && yi >= 0 && yi < Hl) {
                    float bw = w * (dx ? fx : 1.f - fx) * (dy ? fy : 1.f - fy);
                    __half2 v2 = *reinterpret_cast<const __half2*>(
                        &pvalh[(base + (size_t)yi * Wl + xi) * DMODEL + h * HD + ch]);
                    float2 vf = __half22float2(v2);
                    accx = fmaf(bw, vf.x, accx);
                    accy = fmaf(bw, vf.y, accy);
                }
            }
        }
    }
    *reinterpret_cast<__half2*>(&psamph[tok * DMODEL + h * HD + ch]) =
        __floats2half2_rn(accx, accy);
}

// ---------------- fused residual + layernorm ----------------
__global__ void ln_res_kernel(float* __restrict__ px, __half* __restrict__ pxh,
                              const float* __restrict__ y,
                              const float* __restrict__ g, const float* __restrict__ bb,
                              float* __restrict__ outp) {
    int warp = (blockIdx.x * blockDim.x + threadIdx.x) >> 5;
    int lane = threadIdx.x & 31;
    if (warp >= BQ) return;
    size_t base = (size_t)warp * DMODEL;
    float v[8];
    float s = 0.f, s2 = 0.f;
    #pragma unroll
    for (int k = 0; k < 8; ++k) {
        int d = k * 32 + lane;
        v[k] = px[base + d] + y[base + d];
        s += v[k];
        s2 += v[k] * v[k];
    }
    s = wredsum(s);
    s2 = wredsum(s2);
    float m = s * (1.f / DMODEL);
    float var = s2 * (1.f / DMODEL) - m * m;
    float rstd = rsqrtf(var + 1e-5f);
    #pragma unroll
    for (int k = 0; k < 8; ++k) {
        int d = k * 32 + lane;
        float o = (v[k] - m) * rstd * g[d] + bb[d];
        px[base + d]  = o;
        pxh[base + d] = __float2half_rn(o);
        if (outp) outp[base + d] = o;
    }
}

// ---------------- launch ----------------
extern "C" void kernel_launch(void* const* d_in, const int* in_sizes, int n_in,
                              void* d_out, int out_size) {
    (void)n_in; (void)out_size;

    float *px, *ppos, *pol, *pattn, *pff2, *pref, *pbc;
    __half *pxh, *pvalh, *psamph, *pffh, *pwt;
    cudaGetSymbolAddress((void**)&px,    g_x);
    cudaGetSymbolAddress((void**)&ppos,  g_pos);
    cudaGetSymbolAddress((void**)&pol,   g_offlog);
    cudaGetSymbolAddress((void**)&pattn, g_attnout);
    cudaGetSymbolAddress((void**)&pff2,  g_ff2);
    cudaGetSymbolAddress((void**)&pref,  g_ref);
    cudaGetSymbolAddress((void**)&pbc,   g_bcomb);
    cudaGetSymbolAddress((void**)&pxh,   g_xh);
    cudaGetSymbolAddress((void**)&pvalh, g_valh);
    cudaGetSymbolAddress((void**)&psamph,g_samph);
    cudaGetSymbolAddress((void**)&pffh,  g_ffh);
    cudaGetSymbolAddress((void**)&pwt,   g_wt);

    bool interleaved = (in_sizes[1] == in_sizes[0]);
    const float* src[4];
    const float* pos[4];
    for (int i = 0; i < 4; ++i) {
        if (interleaved) {
            src[i] = (const float*)d_in[2 * i];
            pos[i] = (const float*)d_in[2 * i + 1];
        } else {
            src[i] = (const float*)d_in[i];
            pos[i] = (const float*)d_in[4 + i];
        }
    }
    const float* level_embed = (const float*)d_in[8];
    const float* Woff  = (const float*)d_in[9];
    const float* boff  = (const float*)d_in[10];
    const float* Wattn = (const float*)d_in[11];
    const float* battn = (const float*)d_in[12];
    const float* Wv    = (const float*)d_in[13];
    const float* bv    = (const float*)d_in[14];
    const float* Wo    = (const float*)d_in[15];
    const float* bo    = (const float*)d_in[16];
    const float* g1    = (const float*)d_in[17];
    const float* b1    = (const float*)d_in[18];
    const float* W1    = (const float*)d_in[19];
    const float* bb1   = (const float*)d_in[20];
    const float* W2    = (const float*)d_in[21];
    const float* bb2   = (const float*)d_in[22];
    const float* g2    = (const float*)d_in[23];
    const float* b2    = (const float*)d_in[24];
    float* out = (float*)d_out;

    const int hws[4]    = {10000, 2500, 625, 169};
    const int starts[4] = {0, 10000, 12500, 13125};

    for (int l = 0; l < 4; ++l) {
        int total = BATCH * hws[l] * DMODEL;
        flatten_kernel<<<(total + 255) / 256, 256>>>(px, pxh, ppos, src[l], pos[l],
                                                     level_embed + l * DMODEL, starts[l], hws[l]);
    }
    ref_kernel<<<(QTOT + 255) / 256, 256>>>(pref);

    transpose_woa<<<(NLAYERS * 384 * 256 + 255) / 256, 256>>>(pwt, Woff, Wattn);
    transpose_nl<<<(NLAYERS * 256 * 256 + 255) / 256, 256>>>(pwt + OFF_WV, Wv, 256, 256);
    transpose_nl<<<(NLAYERS * 256 * 256 + 255) / 256, 256>>>(pwt + OFF_WO, Wo, 256, 256);
    transpose_nl<<<(NLAYERS * 1024 * 256 + 255) / 256, 256>>>(pwt + OFF_W1, W1, 256, 1024);
    transpose_nl<<<(NLAYERS * 256 * 1024 + 255) / 256, 256>>>(pwt + OFF_W2, W2, 1024, 256);
    bias_comb_kernel<<<(NLAYERS * 384 + 255) / 256, 256>>>(pbc, boff, battn);

    const int warp_grid_deform = (BATCH * QTOT * (NH / 2) + 7) / 8;
    const int warp_grid_ln = (BQ + 7) / 8;

    for (int l = 0; l < NLAYERS; ++l) {
        __half* wt = pwt + (size_t)l * WT_LAYER;
        const float* bcomb_l = pbc + (size_t)l * 384;
        const float* bv_l    = bv  + (size_t)l * DMODEL;
        const float* bo_l    = bo  + (size_t)l * DMODEL;
        const float* bb1_l   = bb1 + (size_t)l * DFF;
        const float* bb2_l   = bb2 + (size_t)l * DMODEL;

        gemm_h_kernel<false, false, true><<<PERSIST_CTAS, 256>>>(
            px, ppos, wt + OFF_WOA, bcomb_l, pol, BQ, 384, 256);
        gemm_h_kernel<false, true, false><<<PERSIST_CTAS, 256>>>(
            pxh, nullptr, wt + OFF_WV, bv_l, pvalh, BQ, 256, 256);

        deform_kernel<<<warp_grid_deform, 256>>>(pvalh, pol, pref, psamph);

        gemm_h_kernel<false, false, false><<<PERSIST_CTAS, 256>>>(
            psamph, nullptr, wt + OFF_WO, bo_l, pattn, BQ, 256, 256);

        ln_res_kernel<<<warp_grid_ln, 256>>>(px, pxh, pattn,
                                             g1 + (size_t)l * DMODEL, b1 + (size_t)l * DMODEL,
                                             nullptr);

        gemm_h_kernel<true, true, false><<<PERSIST_CTAS, 256>>>(
            pxh, nullptr, wt + OFF_W1, bb1_l, pffh, BQ, DFF, 256);
        gemm_h_kernel<false, false, false><<<PERSIST_CTAS, 256>>>(
            pffh, nullptr, wt + OFF_W2, bb2_l, pff2, BQ, 256, 1024);

        ln_res_kernel<<<warp_grid_ln, 256>>>(px, pxh, pff2,
                                             g2 + (size_t)l * DMODEL, b2 + (size_t)l * DMODEL,
                                             (l == NLAYERS - 1) ? out : nullptr);
    }
}

// round 17
// speedup vs baseline: 1.6425x; 1.6425x over previous
#include <cuda_runtime.h>
#include <cuda_fp16.h>
#include <cstdint>

// ---------------- problem constants ----------------
#define QTOT   13294
#define BATCH  2
#define BQ     (BATCH*QTOT)   // 26588
#define DMODEL 256
#define NH     8
#define HD     32
#define DFF    1024
#define NLAYERS 6

__constant__ int c_start[4] = {0, 10000, 12500, 13125};
__constant__ int c_H[4]     = {100, 50, 25, 13};
__constant__ int c_W[4]     = {100, 50, 25, 13};

// ---------------- device scratch ----------------
__device__ float  g_x[BQ * DMODEL];
__device__ float  g_pos[BQ * DMODEL];
__device__ float  g_offlog[BQ * 384];
__device__ float  g_attnout[BQ * DMODEL];
__device__ float  g_ff2[BQ * DMODEL];
__device__ float  g_ref[QTOT * 2];
__device__ float  g_bcomb[NLAYERS * 384];
__device__ __half g_xh[BQ * DMODEL];
__device__ __half g_valh[BQ * DMODEL];
__device__ __half g_samph[BQ * DMODEL];
__device__ __half g_ffh[BQ * DFF];
#define WT_LAYER 753664
#define OFF_WOA 0
#define OFF_WV  98304
#define OFF_WO  163840
#define OFF_W1  229376
#define OFF_W2  491520
__device__ __half g_wt[NLAYERS * WT_LAYER];

// ---------------- helpers ----------------
__device__ __forceinline__ float wredsum(float v) {
    #pragma unroll
    for (int o = 16; o; o >>= 1) v += __shfl_xor_sync(0xffffffffu, v, o);
    return v;
}
__device__ __forceinline__ uint32_t smem_u32(const void* p) {
    uint32_t a;
    asm("{ .reg .u64 t; cvta.to.shared.u64 t, %1; cvt.u32.u64 %0, t; }" : "=r"(a) : "l"(p));
    return a;
}
#define LDSM4(r, addr) \
    asm volatile("ldmatrix.sync.aligned.m8n8.x4.shared.b16 {%0,%1,%2,%3}, [%4];" \
        : "=r"((r)[0]), "=r"((r)[1]), "=r"((r)[2]), "=r"((r)[3]) : "r"(addr))

__device__ __forceinline__ void mma_f16(float* c, const uint32_t* a, const uint32_t* b) {
    asm volatile(
        "mma.sync.aligned.m16n8k16.row.col.f32.f16.f16.f32 "
        "{%0,%1,%2,%3}, {%4,%5,%6,%7}, {%8,%9}, {%0,%1,%2,%3};"
        : "+f"(c[0]), "+f"(c[1]), "+f"(c[2]), "+f"(c[3])
        : "r"(a[0]), "r"(a[1]), "r"(a[2]), "r"(a[3]), "r"(b[0]), "r"(b[1]));
}
__device__ __forceinline__ uint32_t packh2(float a, float b) {
    __half2 h = __floats2half2_rn(a, b);
    return *reinterpret_cast<uint32_t*>(&h);
}
__device__ __forceinline__ void cpasync16(uint32_t dst, const void* src) {
    asm volatile("cp.async.cg.shared.global [%0], [%1], 16;"
                 :: "r"(dst), "l"(src) : "memory");
}
#define CP_COMMIT() asm volatile("cp.async.commit_group;" ::: "memory")
#define CP_WAIT0()  asm volatile("cp.async.wait_group 0;" ::: "memory")
#define CP_WAIT1()  asm volatile("cp.async.wait_group 1;" ::: "memory")

// ---------------- flatten ----------------
__global__ void flatten_kernel(float* __restrict__ px, __half* __restrict__ pxh,
                               float* __restrict__ ppos,
                               const float* __restrict__ src, const float* __restrict__ pos,
                               const float* __restrict__ le, int start, int hw) {
    int idx = blockIdx.x * blockDim.x + threadIdx.x;
    int total = BATCH * hw * DMODEL;
    if (idx >= total) return;
    int d = idx & 255;
    int p = (idx >> 8) % hw;
    int b = idx / (DMODEL * hw);
    size_t sidx = ((size_t)b * DMODEL + d) * hw + p;
    size_t tok  = (size_t)b * QTOT + start + p;
    float v = src[sidx];
    px[tok * DMODEL + d]  = v;
    pxh[tok * DMODEL + d] = __float2half_rn(v);
    ppos[tok * DMODEL + d] = pos[sidx] + le[d];
}

// ---------------- reference points ----------------
__global__ void ref_kernel(float* __restrict__ pref) {
    int q = blockIdx.x * blockDim.x + threadIdx.x;
    if (q >= QTOT) return;
    int l = 3;
    if (q < 10000) l = 0; else if (q < 12500) l = 1; else if (q < 13125) l = 2;
    int loc = q - c_start[l];
    int W = c_W[l];
    int yy = loc / W, xx = loc - yy * W;
    pref[2 * q]     = (xx + 0.5f) / (float)c_W[l];
    pref[2 * q + 1] = (yy + 0.5f) / (float)c_H[l];
}

// ---------------- weight packing ----------------
__global__ void transpose_woa(__half* __restrict__ pwt,
                              const float* __restrict__ woff, const float* __restrict__ wattn) {
    int idx = blockIdx.x * blockDim.x + threadIdx.x;
    int total = NLAYERS * 384 * 256;
    if (idx >= total) return;
    int l = idx / (384 * 256);
    int rem = idx - l * 384 * 256;
    int n = rem >> 8, k = rem & 255;
    float v = (n < 256) ? woff[(size_t)l * 65536 + k * 256 + n]
                        : wattn[(size_t)l * 32768 + k * 128 + (n - 256)];
    pwt[(size_t)l * WT_LAYER + OFF_WOA + n * 256 + k] = __float2half_rn(v);
}
__global__ void transpose_nl(__half* __restrict__ out, const float* __restrict__ in,
                             int K, int N) {
    int idx = blockIdx.x * blockDim.x + threadIdx.x;
    int total = NLAYERS * N * K;
    if (idx >= total) return;
    int l = idx / (N * K);
    int rem = idx - l * N * K;
    int n = rem / K, k = rem - n * K;
    out[(size_t)l * WT_LAYER + n * K + k] = __float2half_rn(in[(size_t)l * K * N + k * N + n]);
}
__global__ void bias_comb_kernel(float* __restrict__ out, const float* __restrict__ boff,
                                 const float* __restrict__ battn) {
    int idx = blockIdx.x * blockDim.x + threadIdx.x;
    if (idx >= NLAYERS * 384) return;
    int l = idx / 384, j = idx - l * 384;
    out[idx] = (j < 256) ? boff[l * 256 + j] : battn[l * 128 + (j - 256)];
}

// ---------------- fp16 mma.sync GEMM body (R13-proven) ----------------
// block 128x128, 8 warps (2M x 4N), warp tile 64x32, mma m16n8k16, KC=32,
// reg-double-buffered staging (FUSE) / cp.async 2-stage (non-FUSE).
#define TM 128
#define TN 128
#define ASTR 40
#define BSTR 40

template<bool RELU, bool HALF_OUT, bool FUSE>
__device__ __forceinline__ void gemm_body(
    const void* __restrict__ Av, const float* __restrict__ A2,
    const __half* __restrict__ Bt,
    const float* __restrict__ bias, void* __restrict__ Cv,
    int M, int N, int K, int m0, int n0,
    __half (*smA)[TM * ASTR], __half (*smB)[TN * BSTR])
{
    int tid = threadIdx.x;
    int wid = tid >> 5, lane = tid & 31;
    int wm = wid & 1, wn = wid >> 1;          // 2 M-warps x 4 N-warps
    int NC = K >> 5;

    int arow = tid >> 1, ahalf = tid & 1;
    int aRowG = m0 + arow;
    int aRowC = (aRowG < M) ? aRowG : (M - 1);
    int bRowG = n0 + arow;

    uint32_t aDst[2], bDst[2];
    #pragma unroll
    for (int s = 0; s < 2; ++s) {
        aDst[s] = smem_u32(&smA[s][arow * ASTR + ahalf * 16]);
        bDst[s] = smem_u32(&smB[s][arow * BSTR + ahalf * 16]);
    }

    float acc[4][4][4];
    #pragma unroll
    for (int i = 0; i < 4; ++i)
        #pragma unroll
        for (int j = 0; j < 4; ++j)
            #pragma unroll
            for (int r = 0; r < 4; ++r) acc[i][j][r] = 0.f;

    uint4 ra0, ra1, rb0, rb1;

    if (FUSE) {
        const float* x = (const float*)Av + (size_t)aRowC * K + ahalf * 16;
        const float* p = A2 + (size_t)aRowC * K + ahalf * 16;
        float4 x0 = *(const float4*)(x), x1 = *(const float4*)(x + 4);
        float4 x2 = *(const float4*)(x + 8), x3 = *(const float4*)(x + 12);
        float4 p0 = *(const float4*)(p), p1 = *(const float4*)(p + 4);
        float4 p2 = *(const float4*)(p + 8), p3 = *(const float4*)(p + 12);
        ra0.x = packh2(x0.x + p0.x, x0.y + p0.y); ra0.y = packh2(x0.z + p0.z, x0.w + p0.w);
        ra0.z = packh2(x1.x + p1.x, x1.y + p1.y); ra0.w = packh2(x1.z + p1.z, x1.w + p1.w);
        ra1.x = packh2(x2.x + p2.x, x2.y + p2.y); ra1.y = packh2(x2.z + p2.z, x2.w + p2.w);
        ra1.z = packh2(x3.x + p3.x, x3.y + p3.y); ra1.w = packh2(x3.z + p3.z, x3.w + p3.w);
        const uint4* bG = (const uint4*)&Bt[(size_t)bRowG * K + ahalf * 16];
        rb0 = bG[0]; rb1 = bG[1];
    } else {
        const char* aS = (const char*)((const __half*)Av + (size_t)aRowC * K + ahalf * 16);
        const char* bS = (const char*)&Bt[(size_t)bRowG * K + ahalf * 16];
        cpasync16(aDst[0],      aS);
        cpasync16(aDst[0] + 16, aS + 16);
        cpasync16(bDst[0],      bS);
        cpasync16(bDst[0] + 16, bS + 16);
        CP_COMMIT();
    }

    int sub = lane >> 3, lrow = lane & 7;

    for (int c = 0; c < NC; ++c) {
        int buf = c & 1;
        if (FUSE) {
            *reinterpret_cast<uint4*>(&smA[buf][arow * ASTR + ahalf * 16])     = ra0;
            *reinterpret_cast<uint4*>(&smA[buf][arow * ASTR + ahalf * 16 + 8]) = ra1;
            *reinterpret_cast<uint4*>(&smB[buf][arow * BSTR + ahalf * 16])     = rb0;
            *reinterpret_cast<uint4*>(&smB[buf][arow * BSTR + ahalf * 16 + 8]) = rb1;
            if (c + 1 < NC) {
                int ko = (c + 1) * 32 + ahalf * 16;
                const float* x = (const float*)Av + (size_t)aRowC * K + ko;
                const float* p = A2 + (size_t)aRowC * K + ko;
                float4 x0 = *(const float4*)(x), x1 = *(const float4*)(x + 4);
                float4 x2 = *(const float4*)(x + 8), x3 = *(const float4*)(x + 12);
                float4 p0 = *(const float4*)(p), p1 = *(const float4*)(p + 4);
                float4 p2 = *(const float4*)(p + 8), p3 = *(const float4*)(p + 12);
                ra0.x = packh2(x0.x + p0.x, x0.y + p0.y); ra0.y = packh2(x0.z + p0.z, x0.w + p0.w);
                ra0.z = packh2(x1.x + p1.x, x1.y + p1.y); ra0.w = packh2(x1.z + p1.z, x1.w + p1.w);
                ra1.x = packh2(x2.x + p2.x, x2.y + p2.y); ra1.y = packh2(x2.z + p2.z, x2.w + p2.w);
                ra1.z = packh2(x3.x + p3.x, x3.y + p3.y); ra1.w = packh2(x3.z + p3.z, x3.w + p3.w);
                const uint4* bG = (const uint4*)&Bt[(size_t)bRowG * K + ko];
                rb0 = bG[0]; rb1 = bG[1];
            }
            __syncthreads();
        } else {
            if (c + 1 < NC) {
                int ko = (c + 1) * 32 + ahalf * 16;
                int nxt = (c + 1) & 1;
                const char* aS = (const char*)((const __half*)Av + (size_t)aRowC * K + ko);
                const char* bS = (const char*)&Bt[(size_t)bRowG * K + ko];
                cpasync16(aDst[nxt],      aS);
                cpasync16(aDst[nxt] + 16, aS + 16);
                cpasync16(bDst[nxt],      bS);
                cpasync16(bDst[nxt] + 16, bS + 16);
                CP_COMMIT();
                CP_WAIT1();
            } else {
                CP_WAIT0();
            }
            __syncthreads();
        }

        const __half* As = smA[buf];
        const __half* Bs = smB[buf];
        #pragma unroll
        for (int ks = 0; ks < 2; ++ks) {
            uint32_t af[4][4];
            #pragma unroll
            for (int mt = 0; mt < 4; ++mt) {
                int r = wm * 64 + mt * 16 + ((sub & 1) << 3) + lrow;
                int col = ks * 16 + ((sub >> 1) << 3);
                LDSM4(af[mt], smem_u32(&As[r * ASTR + col]));
            }
            uint32_t bf[4][2];
            #pragma unroll
            for (int g = 0; g < 2; ++g) {
                int nr = wn * 32 + ((g * 2 + (sub >> 1)) << 3) + lrow;
                int col = ks * 16 + ((sub & 1) << 3);
                uint32_t t[4];
                LDSM4(t, smem_u32(&Bs[nr * BSTR + col]));
                bf[g * 2 + 0][0] = t[0]; bf[g * 2 + 0][1] = t[1];
                bf[g * 2 + 1][0] = t[2]; bf[g * 2 + 1][1] = t[3];
            }
            #pragma unroll
            for (int mt = 0; mt < 4; ++mt)
                #pragma unroll
                for (int nt = 0; nt < 4; ++nt)
                    mma_f16(acc[mt][nt], af[mt], bf[nt]);
        }
        __syncthreads();
    }

    #pragma unroll
    for (int mt = 0; mt < 4; ++mt) {
        int r0 = m0 + wm * 64 + mt * 16 + (lane >> 2);
        int r1 = r0 + 8;
        #pragma unroll
        for (int nt = 0; nt < 4; ++nt) {
            int cb = n0 + wn * 32 + nt * 8 + 2 * (lane & 3);
            float b0 = bias[cb], b1 = bias[cb + 1];
            float v0 = acc[mt][nt][0] + b0;
            float v1 = acc[mt][nt][1] + b1;
            float v2 = acc[mt][nt][2] + b0;
            float v3 = acc[mt][nt][3] + b1;
            if (RELU) {
                v0 = fmaxf(v0, 0.f); v1 = fmaxf(v1, 0.f);
                v2 = fmaxf(v2, 0.f); v3 = fmaxf(v3, 0.f);
            }
            if (HALF_OUT) {
                __half* Ch = (__half*)Cv;
                if (r0 < M)
                    *reinterpret_cast<__half2*>(&Ch[(size_t)r0 * N + cb]) = __floats2half2_rn(v0, v1);
                if (r1 < M)
                    *reinterpret_cast<__half2*>(&Ch[(size_t)r1 * N + cb]) = __floats2half2_rn(v2, v3);
            } else {
                float* Cf = (float*)Cv;
                if (r0 < M)
                    *reinterpret_cast<float2*>(&Cf[(size_t)r0 * N + cb]) = make_float2(v0, v1);
                if (r1 < M)
                    *reinterpret_cast<float2*>(&Cf[(size_t)r1 * N + cb]) = make_float2(v2, v3);
            }
        }
    }
}

// standalone GEMM kernel (Wo, W1, W2)
template<bool RELU, bool HALF_OUT>
__global__ void __launch_bounds__(256) gemm_h_kernel(
    const __half* __restrict__ A, const __half* __restrict__ Bt,
    const float* __restrict__ bias, void* __restrict__ Cv,
    int M, int N, int K)
{
    __shared__ __align__(16) __half smA[2][TM * ASTR];
    __shared__ __align__(16) __half smB[2][TN * BSTR];
    gemm_body<RELU, HALF_OUT, false>(A, nullptr, Bt, bias, Cv,
                                     M, N, K, blockIdx.x * TM, blockIdx.y * TN, smA, smB);
}

// merged WOA(FUSE, N=384) + WV(N=256) kernel: blockIdx.y 0..4
__global__ void __launch_bounds__(256) gemm_woawv_kernel(
    const float* __restrict__ px, const float* __restrict__ ppos,
    const __half* __restrict__ WoaT, const float* __restrict__ bcomb,
    float* __restrict__ pol,
    const __half* __restrict__ pxh, const __half* __restrict__ WvT,
    const float* __restrict__ bv, __half* __restrict__ pvalh,
    int M)
{
    __shared__ __align__(16) __half smA[2][TM * ASTR];
    __shared__ __align__(16) __half smB[2][TN * BSTR];
    if (blockIdx.y < 3) {
        gemm_body<false, false, true>(px, ppos, WoaT, bcomb, pol,
                                      M, 384, 256, blockIdx.x * TM, blockIdx.y * TN, smA, smB);
    } else {
        gemm_body<false, true, false>(pxh, nullptr, WvT, bv, pvalh,
                                      M, 256, 256, blockIdx.x * TM, (blockIdx.y - 3) * TN, smA, smB);
    }
}

// ---------------- deformable attention sampling (dual-head, half2) ----------------
__global__ void deform_kernel(const __half* __restrict__ pvalh, const float* __restrict__ pol,
                              const float* __restrict__ pref, __half* __restrict__ psamph) {
    int gwarp = (blockIdx.x * blockDim.x + threadIdx.x) >> 5;
    int lane = threadIdx.x & 31;
    if (gwarp >= BATCH * QTOT * (NH / 2)) return;
    int hp = gwarp % (NH / 2);
    int q = (gwarp / (NH / 2)) % QTOT;
    int b = gwarp / ((NH / 2) * QTOT);
    int h = hp * 2 + (lane >> 4);
    int ch = (lane & 15) * 2;
    size_t tok = (size_t)b * QTOT + q;

    const float* orow = &pol[tok * 384 + h * 32];
    const float* lrow = &pol[tok * 384 + 256 + h * 16];

    float lg[16];
    float mx = -1e30f;
    #pragma unroll
    for (int i = 0; i < 16; ++i) { lg[i] = __ldg(&lrow[i]); mx = fmaxf(mx, lg[i]); }
    float ssum = 0.f;
    #pragma unroll
    for (int i = 0; i < 16; ++i) { lg[i] = expf(lg[i] - mx); ssum += lg[i]; }
    float inv = 1.f / ssum;

    float rx = pref[2 * q];
    float ry = pref[2 * q + 1];

    float accx = 0.f, accy = 0.f;
    #pragma unroll
    for (int p = 0; p < 16; ++p) {
        int l = p >> 2;
        float w  = lg[p] * inv;
        float ox = __ldg(&orow[2 * p]);
        float oy = __ldg(&orow[2 * p + 1]);
        int Wl = c_W[l], Hl = c_H[l];
        float fw = (float)Wl, fh = (float)Hl;
        float x = (rx + ox / fw) * fw - 0.5f;
        float y = (ry + oy / fh) * fh - 0.5f;
        float x0f = floorf(x), y0f = floorf(y);
        int x0 = (int)x0f, y0 = (int)y0f;
        float fx = x - x0f, fy = y - y0f;
        size_t base = (size_t)b * QTOT + c_start[l];
        #pragma unroll
        for (int dy = 0; dy < 2; ++dy) {
            #pragma unroll
            for (int dx = 0; dx < 2; ++dx) {
                int xi = x0 + dx, yi = y0 + dy;
                if (xi >= 0 && xi < Wl && yi >= 0 && yi < Hl) {
                    float bw = w * (dx ? fx : 1.f - fx) * (dy ? fy : 1.f - fy);
                    __half2 v2 = *reinterpret_cast<const __half2*>(
                        &pvalh[(base + (size_t)yi * Wl + xi) * DMODEL + h * HD + ch]);
                    float2 vf = __half22float2(v2);
                    accx = fmaf(bw, vf.x, accx);
                    accy = fmaf(bw, vf.y, accy);
                }
            }
        }
    }
    *reinterpret_cast<__half2*>(&psamph[tok * DMODEL + h * HD + ch]) =
        __floats2half2_rn(accx, accy);
}

// ---------------- fused residual + layernorm (vectorized) ----------------
__global__ void ln_res_kernel(float* __restrict__ px, __half* __restrict__ pxh,
                              const float* __restrict__ y,
                              const float* __restrict__ g, const float* __restrict__ bb,
                              float* __restrict__ outp) {
    int warp = (blockIdx.x * blockDim.x + threadIdx.x) >> 5;
    int lane = threadIdx.x & 31;
    if (warp >= BQ) return;
    size_t base = (size_t)warp * DMODEL;

    float4 v[2];
    float s = 0.f, s2 = 0.f;
    #pragma unroll
    for (int k = 0; k < 2; ++k) {
        int d = k * 128 + lane * 4;
        float4 xv = *reinterpret_cast<const float4*>(&px[base + d]);
        float4 yv = *reinterpret_cast<const float4*>(&y[base + d]);
        v[k].x = xv.x + yv.x; v[k].y = xv.y + yv.y;
        v[k].z = xv.z + yv.z; v[k].w = xv.w + yv.w;
        s  += v[k].x + v[k].y + v[k].z + v[k].w;
        s2 += v[k].x * v[k].x + v[k].y * v[k].y + v[k].z * v[k].z + v[k].w * v[k].w;
    }
    s = wredsum(s);
    s2 = wredsum(s2);
    float m = s * (1.f / DMODEL);
    float var = s2 * (1.f / DMODEL) - m * m;
    float rstd = rsqrtf(var + 1e-5f);

    #pragma unroll
    for (int k = 0; k < 2; ++k) {
        int d = k * 128 + lane * 4;
        float4 gv = *reinterpret_cast<const float4*>(&g[d]);
        float4 bv = *reinterpret_cast<const float4*>(&bb[d]);
        float4 o;
        o.x = (v[k].x - m) * rstd * gv.x + bv.x;
        o.y = (v[k].y - m) * rstd * gv.y + bv.y;
        o.z = (v[k].z - m) * rstd * gv.z + bv.z;
        o.w = (v[k].w - m) * rstd * gv.w + bv.w;
        *reinterpret_cast<float4*>(&px[base + d]) = o;
        uint2 h4;
        h4.x = packh2(o.x, o.y);
        h4.y = packh2(o.z, o.w);
        *reinterpret_cast<uint2*>(&pxh[base + d]) = h4;
        if (outp) *reinterpret_cast<float4*>(&outp[base + d]) = o;
    }
}

// ---------------- launch ----------------
extern "C" void kernel_launch(void* const* d_in, const int* in_sizes, int n_in,
                              void* d_out, int out_size) {
    (void)n_in; (void)out_size;

    float *px, *ppos, *pol, *pattn, *pff2, *pref, *pbc;
    __half *pxh, *pvalh, *psamph, *pffh, *pwt;
    cudaGetSymbolAddress((void**)&px,    g_x);
    cudaGetSymbolAddress((void**)&ppos,  g_pos);
    cudaGetSymbolAddress((void**)&pol,   g_offlog);
    cudaGetSymbolAddress((void**)&pattn, g_attnout);
    cudaGetSymbolAddress((void**)&pff2,  g_ff2);
    cudaGetSymbolAddress((void**)&pref,  g_ref);
    cudaGetSymbolAddress((void**)&pbc,   g_bcomb);
    cudaGetSymbolAddress((void**)&pxh,   g_xh);
    cudaGetSymbolAddress((void**)&pvalh, g_valh);
    cudaGetSymbolAddress((void**)&psamph,g_samph);
    cudaGetSymbolAddress((void**)&pffh,  g_ffh);
    cudaGetSymbolAddress((void**)&pwt,   g_wt);

    bool interleaved = (in_sizes[1] == in_sizes[0]);
    const float* src[4];
    const float* pos[4];
    for (int i = 0; i < 4; ++i) {
        if (interleaved) {
            src[i] = (const float*)d_in[2 * i];
            pos[i] = (const float*)d_in[2 * i + 1];
        } else {
            src[i] = (const float*)d_in[i];
            pos[i] = (const float*)d_in[4 + i];
        }
    }
    const float* level_embed = (const float*)d_in[8];
    const float* Woff  = (const float*)d_in[9];
    const float* boff  = (const float*)d_in[10];
    const float* Wattn = (const float*)d_in[11];
    const float* battn = (const float*)d_in[12];
    const float* Wv    = (const float*)d_in[13];
    const float* bv    = (const float*)d_in[14];
    const float* Wo    = (const float*)d_in[15];
    const float* bo    = (const float*)d_in[16];
    const float* g1    = (const float*)d_in[17];
    const float* b1    = (const float*)d_in[18];
    const float* W1    = (const float*)d_in[19];
    const float* bb1   = (const float*)d_in[20];
    const float* W2    = (const float*)d_in[21];
    const float* bb2   = (const float*)d_in[22];
    const float* g2    = (const float*)d_in[23];
    const float* b2    = (const float*)d_in[24];
    float* out = (float*)d_out;

    const int hws[4]    = {10000, 2500, 625, 169};
    const int starts[4] = {0, 10000, 12500, 13125};

    for (int l = 0; l < 4; ++l) {
        int total = BATCH * hws[l] * DMODEL;
        flatten_kernel<<<(total + 255) / 256, 256>>>(px, pxh, ppos, src[l], pos[l],
                                                     level_embed + l * DMODEL, starts[l], hws[l]);
    }
    ref_kernel<<<(QTOT + 255) / 256, 256>>>(pref);

    transpose_woa<<<(NLAYERS * 384 * 256 + 255) / 256, 256>>>(pwt, Woff, Wattn);
    transpose_nl<<<(NLAYERS * 256 * 256 + 255) / 256, 256>>>(pwt + OFF_WV, Wv, 256, 256);
    transpose_nl<<<(NLAYERS * 256 * 256 + 255) / 256, 256>>>(pwt + OFF_WO, Wo, 256, 256);
    transpose_nl<<<(NLAYERS * 1024 * 256 + 255) / 256, 256>>>(pwt + OFF_W1, W1, 256, 1024);
    transpose_nl<<<(NLAYERS * 256 * 1024 + 255) / 256, 256>>>(pwt + OFF_W2, W2, 1024, 256);
    bias_comb_kernel<<<(NLAYERS * 384 + 255) / 256, 256>>>(pbc, boff, battn);

    const int mblocks = (BQ + TM - 1) / TM;                          // 208
    const int warp_grid_deform = (BATCH * QTOT * (NH / 2) + 7) / 8;
    const int warp_grid_ln = (BQ + 7) / 8;

    for (int l = 0; l < NLAYERS; ++l) {
        __half* wt = pwt + (size_t)l * WT_LAYER;
        const float* bcomb_l = pbc + (size_t)l * 384;
        const float* bv_l    = bv  + (size_t)l * DMODEL;
        const float* bo_l    = bo  + (size_t)l * DMODEL;
        const float* bb1_l   = bb1 + (size_t)l * DFF;
        const float* bb2_l   = bb2 + (size_t)l * DMODEL;

        // merged WOA (N=384, FUSE) + WV (N=256): grid.y = 3 + 2
        gemm_woawv_kernel<<<dim3(mblocks, 5), 256>>>(
            px, ppos, wt + OFF_WOA, bcomb_l, pol,
            pxh, wt + OFF_WV, bv_l, pvalh, BQ);

        deform_kernel<<<warp_grid_deform, 256>>>(pvalh, pol, pref, psamph);

        gemm_h_kernel<false, false><<<dim3(mblocks, 2), 256>>>(
            psamph, wt + OFF_WO, bo_l, pattn, BQ, 256, 256);

        ln_res_kernel<<<warp_grid_ln, 256>>>(px, pxh, pattn,
                                             g1 + (size_t)l * DMODEL, b1 + (size_t)l * DMODEL,
                                             nullptr);

        gemm_h_kernel<true, true><<<dim3(mblocks, 8), 256>>>(
            pxh, wt + OFF_W1, bb1_l, pffh, BQ, DFF, 256);
        gemm_h_kernel<false, false><<<dim3(mblocks, 2), 256>>>(
            pffh, wt + OFF_W2, bb2_l, pff2, BQ, 256, 1024);

        ln_res_kernel<<<warp_grid_ln, 256>>>(px, pxh, pff2,
                                             g2 + (size_t)l * DMODEL, b2 + (size_t)l * DMODEL,
                                             (l == NLAYERS - 1) ? out : nullptr);
    }
}